// round 9
// baseline (speedup 1.0000x reference)
#include <cuda_runtime.h>
#include <cuda_bf16.h>

// Circular self-convolution via packed real FFT (two real rows per complex
// transform), one row-pair per CTA, 192 CTAs, 512 threads.
//
// R9 = R8's half-split parallelism (each thread computes 2 of 4 butterfly
// outputs; 16 warps/CTA hide the LDS->FMA->STS chain) + PING-PONG double
// buffering to fix R8's race: every stage reads buffer A and writes buffer
// B, so no thread ever overwrites data another thread still needs. One
// __syncthreads per stage, same barrier count as the in-place version.
//
// Structure: radix-4 DIF forward (natural in, digit-reversed out), conj-
// symmetry unpack + square + repack in the permuted basis, exact stage-by-
// stage inverse, 1/1024 folded into the final gmem store.

#define N_CONV 1024
#define THREADS 512

// Padded smem index: +1 float per 32 to break stride conflicts.
#define P(i) ((i) + ((i) >> 5))

__device__ __forceinline__ int rev4(int p) {
    return ((p & 3) << 8) | (((p >> 2) & 3) << 6) | (((p >> 4) & 3) << 4)
         | (((p >> 6) & 3) << 2) | ((p >> 8) & 3);
}

// Forward DIF stage, half-split, src -> dst.
template<int L>
__device__ __forceinline__ void fwd_stage(const float* Sr, const float* Si,
                                          float* Dr, float* Di,
                                          const float* Wr, const float* Wi,
                                          int t, int half)
{
    const int q   = L >> 2;
    const int tws = N_CONV / L;
    const int blk  = t / q;
    const int pos  = t - blk * q;
    const int base = blk * L + pos;
    const int w1   = pos * tws;

    const float a0r = Sr[P(base)],       a0i = Si[P(base)];
    const float a1r = Sr[P(base + q)],   a1i = Si[P(base + q)];
    const float a2r = Sr[P(base + 2*q)], a2i = Si[P(base + 2*q)];
    const float a3r = Sr[P(base + 3*q)], a3i = Si[P(base + 3*q)];

    if (half == 0) {
        const float t0r = a0r + a2r, t0i = a0i + a2i;
        const float t2r = a1r + a3r, t2i = a1i + a3i;
        Dr[P(base)] = t0r + t2r;
        Di[P(base)] = t0i + t2i;
        const float t1r = a0r - a2r, t1i = a0i - a2i;
        const float t3r = a1r - a3r, t3i = a1i - a3i;
        const float o1r = t1r + t3i, o1i = t1i - t3r;   // t1 - i*t3
        const float c = Wr[w1], d = Wi[w1];
        Dr[P(base + q)] = o1r * c - o1i * d;
        Di[P(base + q)] = o1r * d + o1i * c;
    } else {
        const float t0r = a0r + a2r, t0i = a0i + a2i;
        const float t2r = a1r + a3r, t2i = a1i + a3i;
        const float o2r = t0r - t2r, o2i = t0i - t2i;
        float c = Wr[2 * w1], d = Wi[2 * w1];
        Dr[P(base + 2*q)] = o2r * c - o2i * d;
        Di[P(base + 2*q)] = o2r * d + o2i * c;
        const float t1r = a0r - a2r, t1i = a0i - a2i;
        const float t3r = a1r - a3r, t3i = a1i - a3i;
        const float o3r = t1r - t3i, o3i = t1i + t3r;   // t1 + i*t3
        c = Wr[3 * w1]; d = Wi[3 * w1];
        Dr[P(base + 3*q)] = o3r * c - o3i * d;
        Di[P(base + 3*q)] = o3r * d + o3i * c;
    }
}

// Inverse stage (un-twiddle, inverse butterfly), half-split, src -> dst.
template<int L>
__device__ __forceinline__ void inv_stage(const float* Sr, const float* Si,
                                          float* Dr, float* Di,
                                          const float* Wr, const float* Wi,
                                          int t, int half)
{
    const int q   = L >> 2;
    const int tws = N_CONV / L;
    const int blk  = t / q;
    const int pos  = t - blk * q;
    const int base = blk * L + pos;
    const int w1   = pos * tws;

    const float a0r = Sr[P(base)],  a0i = Si[P(base)];
    float a1r = Sr[P(base + q)],    a1i = Si[P(base + q)];
    float a2r = Sr[P(base + 2*q)],  a2i = Si[P(base + 2*q)];
    float a3r = Sr[P(base + 3*q)],  a3i = Si[P(base + 3*q)];

    // Un-twiddle by conj(W) = (c, -d).
    float c, d, r;
    c = Wr[w1];     d = Wi[w1];     r = a1r;
    a1r = r*c + a1i*d;  a1i = a1i*c - r*d;
    c = Wr[2*w1];   d = Wi[2*w1];   r = a2r;
    a2r = r*c + a2i*d;  a2i = a2i*c - r*d;
    c = Wr[3*w1];   d = Wi[3*w1];   r = a3r;
    a3r = r*c + a3i*d;  a3i = a3i*c - r*d;

    const float t0r = a0r + a2r, t0i = a0i + a2i;
    const float t1r = a0r - a2r, t1i = a0i - a2i;
    const float t2r = a1r + a3r, t2i = a1i + a3i;
    const float t3r = a1r - a3r, t3i = a1i - a3i;

    if (half == 0) {
        Dr[P(base)]       = t0r + t2r;  Di[P(base)]       = t0i + t2i;
        Dr[P(base + q)]   = t1r - t3i;  Di[P(base + q)]   = t1i + t3r;  // +i*t3
    } else {
        Dr[P(base + 2*q)] = t0r - t2r;  Di[P(base + 2*q)] = t0i - t2i;
        Dr[P(base + 3*q)] = t1r + t3i;  Di[P(base + 3*q)] = t1i - t3r;  // -i*t3
    }
}

__global__ __launch_bounds__(THREADS, 2)
void mcf_fft4_kernel(const float* __restrict__ x1,
                     const float* __restrict__ x2,
                     const float* __restrict__ x3,
                     float* __restrict__ out)
{
    // Ping-pong buffers A (index 0) and B (index 1).
    __shared__ __align__(16) float XrA[1056], XiA[1056];
    __shared__ __align__(16) float XrB[1056], XiB[1056];
    __shared__ __align__(16) float Wr[1024], Wi[1024];

    const int bx = blockIdx.x;             // 0..191: row pair
    const int rA = 2 * bx;
    const int arr = rA >> 7;
    const int lA  = rA & 127;

    const float* x  = (arr == 0) ? x1 : ((arr == 1) ? x2 : x3);
    const float* xa = x + (size_t)lA * N_CONV;
    const float* xb = xa + N_CONV;

    const int s    = threadIdx.x;          // 0..511
    const int t    = s & 255;
    const int half = s >> 8;

    // Twiddles: thread s computes W^s once; W^(s+512) = -W^s.
    {
        float sn, cs;
        sincospif((float)s * (1.0f / 512.0f), &sn, &cs);
        Wr[s]       = cs;   Wi[s]       = -sn;
        Wr[s + 512] = -cs;  Wi[s + 512] = sn;
        // Packed input z = xa + i*xb into buffer A.
        XrA[P(s)]       = xa[s];        XiA[P(s)]       = xb[s];
        XrA[P(s + 512)] = xa[s + 512];  XiA[P(s + 512)] = xb[s + 512];
    }
    __syncthreads();

    // Forward DIF stages, ping-pong A->B->A->...
    fwd_stage<1024>(XrA, XiA, XrB, XiB, Wr, Wi, t, half); __syncthreads();
    fwd_stage< 256>(XrB, XiB, XrA, XiA, Wr, Wi, t, half); __syncthreads();
    fwd_stage<  64>(XrA, XiA, XrB, XiB, Wr, Wi, t, half); __syncthreads();
    fwd_stage<  16>(XrB, XiB, XrA, XiA, Wr, Wi, t, half); __syncthreads();
    fwd_stage<   4>(XrA, XiA, XrB, XiB, Wr, Wi, t, half); __syncthreads();

    // Middle: conj-symmetry unpack, square, repack. Reads B, writes A.
    {
        #pragma unroll
        for (int m = 0; m < 2; ++m) {
            const int p  = s + 512 * m;
            const int k  = rev4(p);
            const int pm = rev4((N_CONV - k) & (N_CONV - 1));

            const float Zr = XrB[P(p)],  Zi = XiB[P(p)];
            const float Mr = XrB[P(pm)], Mi = XiB[P(pm)];

            // Xa = (Z + conj(M))/2 ; Xb = (Z - conj(M))/(2i)
            const float Ar = 0.5f * (Zr + Mr), Ai = 0.5f * (Zi - Mi);
            const float Br = 0.5f * (Zi + Mi), Bi = 0.5f * (Mr - Zr);

            const float Yar = Ar*Ar - Ai*Ai, Yai = 2.0f*Ar*Ai;
            const float Ybr = Br*Br - Bi*Bi, Ybi = 2.0f*Br*Bi;
            XrA[P(p)] = Yar - Ybi;     // Y = Ya + i*Yb
            XiA[P(p)] = Yai + Ybr;
        }
    }
    __syncthreads();

    // Inverse stages, ping-pong A->B->A->B->A.
    inv_stage<   4>(XrA, XiA, XrB, XiB, Wr, Wi, t, half); __syncthreads();
    inv_stage<  16>(XrB, XiB, XrA, XiA, Wr, Wi, t, half); __syncthreads();
    inv_stage<  64>(XrA, XiA, XrB, XiB, Wr, Wi, t, half); __syncthreads();
    inv_stage< 256>(XrB, XiB, XrA, XiA, Wr, Wi, t, half); __syncthreads();

    // Final inverse stage L=1024 (q=256, pos=t): read A, write both gmem rows.
    {
        const float a0r = XrA[P(t)],       a0i = XiA[P(t)];
        float a1r = XrA[P(t + 256)],       a1i = XiA[P(t + 256)];
        float a2r = XrA[P(t + 512)],       a2i = XiA[P(t + 512)];
        float a3r = XrA[P(t + 768)],       a3i = XiA[P(t + 768)];

        float c, d, r;
        c = Wr[t];     d = Wi[t];     r = a1r;
        a1r = r*c + a1i*d;  a1i = a1i*c - r*d;
        c = Wr[2*t];   d = Wi[2*t];   r = a2r;
        a2r = r*c + a2i*d;  a2i = a2i*c - r*d;
        c = Wr[3*t];   d = Wi[3*t];   r = a3r;
        a3r = r*c + a3i*d;  a3i = a3i*c - r*d;

        const float inv_n = 1.0f / 1024.0f;
        float* orowA = out + (size_t)arr * 128 * N_CONV + (size_t)lA * N_CONV;
        float* orowB = orowA + N_CONV;

        if (half == 0) {
            const float t0r = a0r + a2r, t0i = a0i + a2i;
            const float t2r = a1r + a3r, t2i = a1i + a3i;
            orowA[t]       = (t0r + t2r) * inv_n;
            orowB[t]       = (t0i + t2i) * inv_n;
            orowA[t + 512] = (t0r - t2r) * inv_n;
            orowB[t + 512] = (t0i - t2i) * inv_n;
        } else {
            const float t1r = a0r - a2r, t1i = a0i - a2i;
            const float t3r = a1r - a3r, t3i = a1i - a3i;
            orowA[t + 256] = (t1r - t3i) * inv_n;
            orowB[t + 256] = (t1i + t3r) * inv_n;
            orowA[t + 768] = (t1r + t3i) * inv_n;
            orowB[t + 768] = (t1i - t3r) * inv_n;
        }
    }
}

extern "C" void kernel_launch(void* const* d_in, const int* in_sizes, int n_in,
                              void* d_out, int out_size)
{
    const float* x1 = (const float*)d_in[0];
    const float* x2 = (const float*)d_in[1];
    const float* x3 = (const float*)d_in[2];
    float* out = (float*)d_out;

    mcf_fft4_kernel<<<192, THREADS>>>(x1, x2, x3, out);
}

// round 10
// speedup vs baseline: 1.4928x; 1.4928x over previous
#include <cuda_runtime.h>
#include <cuda_bf16.h>

// Circular self-convolution via packed real FFT (two real rows per complex
// transform). 192 CTAs x 256 threads, one transform per CTA (R7 skeleton:
// each thread exclusively owns its butterfly's 4 points -> in-place safe).
//
// R10 cuts the instruction stream (the binding resource per R8/R9 evidence):
//  - interleaved float2 complex in smem: LDS.64/STS.64 halves smem ops
//  - fwd L=4 + mirror-square + inv L=4 fused around the middle (both L=4
//    stages have identity twiddles); Z kept in registers across the sync
//  - twiddle prologue: 1 sincospif/thread + quarter-wave symmetry
//  - light padding P2(i)=i+(i>>4); 2 CTAs/SM co-residency via launch_bounds

#define N_CONV 1024
#define THREADS 256

#define P2(i) ((i) + ((i) >> 4))

__device__ __forceinline__ int rev4(int p) {
    return ((p & 3) << 8) | (((p >> 2) & 3) << 6) | (((p >> 4) & 3) << 4)
         | (((p >> 6) & 3) << 2) | ((p >> 8) & 3);
}

// Forward DIF radix-4 stage, in-place, float2.
template<int L>
__device__ __forceinline__ void fwd_stage(float2* X, const float2* W, int t)
{
    const int q    = L >> 2;
    const int blk  = t / q;
    const int pos  = t % q;
    const int base = blk * L + pos;
    const int w1   = pos * (N_CONV / L);

    const float2 a0 = X[P2(base)];
    const float2 a1 = X[P2(base + q)];
    const float2 a2 = X[P2(base + 2*q)];
    const float2 a3 = X[P2(base + 3*q)];

    const float t0r = a0.x + a2.x, t0i = a0.y + a2.y;
    const float t1r = a0.x - a2.x, t1i = a0.y - a2.y;
    const float t2r = a1.x + a3.x, t2i = a1.y + a3.y;
    const float t3r = a1.x - a3.x, t3i = a1.y - a3.y;

    X[P2(base)] = make_float2(t0r + t2r, t0i + t2i);

    const float o1r = t1r + t3i, o1i = t1i - t3r;   // t1 - i*t3
    const float o2r = t0r - t2r, o2i = t0i - t2i;
    const float o3r = t1r - t3i, o3i = t1i + t3r;   // t1 + i*t3

    float2 w = W[P2(w1)];
    X[P2(base + q)]   = make_float2(o1r*w.x - o1i*w.y, o1r*w.y + o1i*w.x);
    w = W[P2(2*w1)];
    X[P2(base + 2*q)] = make_float2(o2r*w.x - o2i*w.y, o2r*w.y + o2i*w.x);
    w = W[P2(3*w1)];
    X[P2(base + 3*q)] = make_float2(o3r*w.x - o3i*w.y, o3r*w.y + o3i*w.x);
}

// Inverse stage: un-twiddle by conj(W), inverse butterfly. In-place, float2.
template<int L>
__device__ __forceinline__ void inv_stage(float2* X, const float2* W, int t)
{
    const int q    = L >> 2;
    const int blk  = t / q;
    const int pos  = t % q;
    const int base = blk * L + pos;
    const int w1   = pos * (N_CONV / L);

    const float2 a0 = X[P2(base)];
    float2 a1 = X[P2(base + q)];
    float2 a2 = X[P2(base + 2*q)];
    float2 a3 = X[P2(base + 3*q)];

    float2 w; float r;
    w = W[P2(w1)];   r = a1.x;
    a1.x = r*w.x + a1.y*w.y;  a1.y = a1.y*w.x - r*w.y;
    w = W[P2(2*w1)]; r = a2.x;
    a2.x = r*w.x + a2.y*w.y;  a2.y = a2.y*w.x - r*w.y;
    w = W[P2(3*w1)]; r = a3.x;
    a3.x = r*w.x + a3.y*w.y;  a3.y = a3.y*w.x - r*w.y;

    const float t0r = a0.x + a2.x, t0i = a0.y + a2.y;
    const float t1r = a0.x - a2.x, t1i = a0.y - a2.y;
    const float t2r = a1.x + a3.x, t2i = a1.y + a3.y;
    const float t3r = a1.x - a3.x, t3i = a1.y - a3.y;

    X[P2(base)]       = make_float2(t0r + t2r, t0i + t2i);
    X[P2(base + q)]   = make_float2(t1r - t3i, t1i + t3r);
    X[P2(base + 2*q)] = make_float2(t0r - t2r, t0i - t2i);
    X[P2(base + 3*q)] = make_float2(t1r + t3i, t1i - t3r);
}

__global__ __launch_bounds__(THREADS, 2)
void mcf_fft5_kernel(const float* __restrict__ x1,
                     const float* __restrict__ x2,
                     const float* __restrict__ x3,
                     float* __restrict__ out)
{
    __shared__ __align__(16) float2 X[1088];   // 1024 + padding
    __shared__ __align__(16) float2 W[1088];

    const int bx = blockIdx.x;             // 0..191: one transform (row pair)
    const int gr  = 2 * bx;
    const int arr = gr >> 7;
    const int lA  = gr & 127;

    const float* xp = (arr == 0) ? x1 : ((arr == 1) ? x2 : x3);
    const float* xa = xp + (size_t)lA * N_CONV;
    const float* xb = xa + N_CONV;

    const int t = threadIdx.x;

    // Twiddles: one sincospif, quarter-wave symmetry fills all 1024.
    // W^k = (c, -s); W^{k+256} = -i W^k = (-s, -c); W^{k+512} = (-c, s);
    // W^{k+768} = i W^k = (s, c).
    {
        float sn, cs;
        sincospif((float)t * (1.0f / 512.0f), &sn, &cs);
        W[P2(t)]       = make_float2(cs, -sn);
        W[P2(t + 256)] = make_float2(-sn, -cs);
        W[P2(t + 512)] = make_float2(-cs, sn);
        W[P2(t + 768)] = make_float2(sn, cs);
        // Packed input z = xa + i*xb.
        #pragma unroll
        for (int m = 0; m < 4; ++m) {
            const int s4 = t + 256 * m;
            X[P2(s4)] = make_float2(xa[s4], xb[s4]);
        }
    }
    __syncthreads();

    // Forward DIF stages.
    fwd_stage<1024>(X, W, t); __syncthreads();
    fwd_stage< 256>(X, W, t); __syncthreads();
    fwd_stage<  64>(X, W, t); __syncthreads();
    fwd_stage<  16>(X, W, t); __syncthreads();

    // Fused fwd L=4 (identity twiddles): keep Z in registers, publish to smem.
    float2 Z[4];
    {
        const int b = 4 * t;
        const float2 a0 = X[P2(b)],   a1 = X[P2(b + 1)];
        const float2 a2 = X[P2(b + 2)], a3 = X[P2(b + 3)];
        const float t0r = a0.x + a2.x, t0i = a0.y + a2.y;
        const float t1r = a0.x - a2.x, t1i = a0.y - a2.y;
        const float t2r = a1.x + a3.x, t2i = a1.y + a3.y;
        const float t3r = a1.x - a3.x, t3i = a1.y - a3.y;
        Z[0] = make_float2(t0r + t2r, t0i + t2i);
        Z[1] = make_float2(t1r + t3i, t1i - t3r);   // o1 = t1 - i*t3
        Z[2] = make_float2(t0r - t2r, t0i - t2i);
        Z[3] = make_float2(t1r - t3i, t1i + t3r);   // o3 = t1 + i*t3
        X[P2(b)]     = Z[0];
        X[P2(b + 1)] = Z[1];
        X[P2(b + 2)] = Z[2];
        X[P2(b + 3)] = Z[3];
    }
    __syncthreads();

    // Middle: conj-symmetry unpack + square + repack (Z local, mirror from
    // smem), then fused inv L=4 (identity twiddles) after the sync.
    float2 Y[4];
    {
        #pragma unroll
        for (int j = 0; j < 4; ++j) {
            const int p  = 4 * t + j;
            const int k  = rev4(p);
            const int pm = rev4((N_CONV - k) & (N_CONV - 1));

            const float2 Zp = Z[j];
            const float2 M  = X[P2(pm)];

            // Xa = (Z + conj(M))/2 ; Xb = (Z - conj(M))/(2i)
            const float Ar = 0.5f * (Zp.x + M.x), Ai = 0.5f * (Zp.y - M.y);
            const float Br = 0.5f * (Zp.y + M.y), Bi = 0.5f * (M.x - Zp.x);

            const float Yar = Ar*Ar - Ai*Ai, Yai = 2.0f*Ar*Ai;
            const float Ybr = Br*Br - Bi*Bi, Ybi = 2.0f*Br*Bi;
            Y[j] = make_float2(Yar - Ybi, Yai + Ybr);   // Y = Ya + i*Yb
        }
    }
    __syncthreads();   // all mirror reads complete before in-place writes
    {
        const int b = 4 * t;
        const float t0r = Y[0].x + Y[2].x, t0i = Y[0].y + Y[2].y;
        const float t1r = Y[0].x - Y[2].x, t1i = Y[0].y - Y[2].y;
        const float t2r = Y[1].x + Y[3].x, t2i = Y[1].y + Y[3].y;
        const float t3r = Y[1].x - Y[3].x, t3i = Y[1].y - Y[3].y;
        X[P2(b)]     = make_float2(t0r + t2r, t0i + t2i);
        X[P2(b + 1)] = make_float2(t1r - t3i, t1i + t3r);
        X[P2(b + 2)] = make_float2(t0r - t2r, t0i - t2i);
        X[P2(b + 3)] = make_float2(t1r + t3i, t1i - t3r);
    }
    __syncthreads();

    // Inverse stages.
    inv_stage<  16>(X, W, t); __syncthreads();
    inv_stage<  64>(X, W, t); __syncthreads();
    inv_stage< 256>(X, W, t); __syncthreads();

    // Final inverse stage L=1024 (q=256, pos=t): write both rows to gmem.
    {
        const float2 a0 = X[P2(t)];
        float2 a1 = X[P2(t + 256)];
        float2 a2 = X[P2(t + 512)];
        float2 a3 = X[P2(t + 768)];

        float2 w; float r;
        w = W[P2(t)];     r = a1.x;
        a1.x = r*w.x + a1.y*w.y;  a1.y = a1.y*w.x - r*w.y;
        w = W[P2(2*t)];   r = a2.x;
        a2.x = r*w.x + a2.y*w.y;  a2.y = a2.y*w.x - r*w.y;
        w = W[P2(3*t)];   r = a3.x;
        a3.x = r*w.x + a3.y*w.y;  a3.y = a3.y*w.x - r*w.y;

        const float t0r = a0.x + a2.x, t0i = a0.y + a2.y;
        const float t1r = a0.x - a2.x, t1i = a0.y - a2.y;
        const float t2r = a1.x + a3.x, t2i = a1.y + a3.y;
        const float t3r = a1.x - a3.x, t3i = a1.y - a3.y;

        const float inv_n = 1.0f / 1024.0f;
        float* orowA = out + (size_t)arr * 128 * N_CONV + (size_t)lA * N_CONV;
        float* orowB = orowA + N_CONV;

        orowA[t]       = (t0r + t2r) * inv_n;
        orowB[t]       = (t0i + t2i) * inv_n;
        orowA[t + 256] = (t1r - t3i) * inv_n;
        orowB[t + 256] = (t1i + t3r) * inv_n;
        orowA[t + 512] = (t0r - t2r) * inv_n;
        orowB[t + 512] = (t0i - t2i) * inv_n;
        orowA[t + 768] = (t1r + t3i) * inv_n;
        orowB[t + 768] = (t1i - t3r) * inv_n;
    }
}

extern "C" void kernel_launch(void* const* d_in, const int* in_sizes, int n_in,
                              void* d_out, int out_size)
{
    const float* x1 = (const float*)d_in[0];
    const float* x2 = (const float*)d_in[1];
    const float* x3 = (const float*)d_in[2];
    float* out = (float*)d_out;

    mcf_fft5_kernel<<<192, THREADS>>>(x1, x2, x3, out);
}

// round 11
// speedup vs baseline: 1.6148x; 1.0817x over previous
#include <cuda_runtime.h>
#include <cuda_bf16.h>

// Circular self-convolution via packed real FFT (two real rows per complex
// transform). 192 CTAs x 256 threads, one transform per CTA.
//
// R11 = R10 + barrier-scope reduction: with thread t owning points 4t..4t+3,
// warp w touches only its 128-point block during stages L=64,16,4 (fwd and
// inv). Those boundaries use __syncwarp (cheap, no cross-warp skew) instead
// of __syncthreads. Only the global boundaries (L=1024, L=256, middle
// mirror, inv256, final) keep block barriers: 7 instead of 11. Warp-local
// stages chain back-to-back -> cross-stage latency overlap.
// Also: prologue uses float4 gmem loads (2x LDG.128/thread instead of 8x
// LDG.32). Arithmetic identical to R10 (rel_err must match exactly).

#define N_CONV 1024
#define THREADS 256

#define P2(i) ((i) + ((i) >> 4))

__device__ __forceinline__ int rev4(int p) {
    return ((p & 3) << 8) | (((p >> 2) & 3) << 6) | (((p >> 4) & 3) << 4)
         | (((p >> 6) & 3) << 2) | ((p >> 8) & 3);
}

// Forward DIF radix-4 stage, in-place, float2.
template<int L>
__device__ __forceinline__ void fwd_stage(float2* X, const float2* W, int t)
{
    const int q    = L >> 2;
    const int blk  = t / q;
    const int pos  = t % q;
    const int base = blk * L + pos;
    const int w1   = pos * (N_CONV / L);

    const float2 a0 = X[P2(base)];
    const float2 a1 = X[P2(base + q)];
    const float2 a2 = X[P2(base + 2*q)];
    const float2 a3 = X[P2(base + 3*q)];

    const float t0r = a0.x + a2.x, t0i = a0.y + a2.y;
    const float t1r = a0.x - a2.x, t1i = a0.y - a2.y;
    const float t2r = a1.x + a3.x, t2i = a1.y + a3.y;
    const float t3r = a1.x - a3.x, t3i = a1.y - a3.y;

    X[P2(base)] = make_float2(t0r + t2r, t0i + t2i);

    const float o1r = t1r + t3i, o1i = t1i - t3r;   // t1 - i*t3
    const float o2r = t0r - t2r, o2i = t0i - t2i;
    const float o3r = t1r - t3i, o3i = t1i + t3r;   // t1 + i*t3

    float2 w = W[P2(w1)];
    X[P2(base + q)]   = make_float2(o1r*w.x - o1i*w.y, o1r*w.y + o1i*w.x);
    w = W[P2(2*w1)];
    X[P2(base + 2*q)] = make_float2(o2r*w.x - o2i*w.y, o2r*w.y + o2i*w.x);
    w = W[P2(3*w1)];
    X[P2(base + 3*q)] = make_float2(o3r*w.x - o3i*w.y, o3r*w.y + o3i*w.x);
}

// Inverse stage: un-twiddle by conj(W), inverse butterfly. In-place, float2.
template<int L>
__device__ __forceinline__ void inv_stage(float2* X, const float2* W, int t)
{
    const int q    = L >> 2;
    const int blk  = t / q;
    const int pos  = t % q;
    const int base = blk * L + pos;
    const int w1   = pos * (N_CONV / L);

    const float2 a0 = X[P2(base)];
    float2 a1 = X[P2(base + q)];
    float2 a2 = X[P2(base + 2*q)];
    float2 a3 = X[P2(base + 3*q)];

    float2 w; float r;
    w = W[P2(w1)];   r = a1.x;
    a1.x = r*w.x + a1.y*w.y;  a1.y = a1.y*w.x - r*w.y;
    w = W[P2(2*w1)]; r = a2.x;
    a2.x = r*w.x + a2.y*w.y;  a2.y = a2.y*w.x - r*w.y;
    w = W[P2(3*w1)]; r = a3.x;
    a3.x = r*w.x + a3.y*w.y;  a3.y = a3.y*w.x - r*w.y;

    const float t0r = a0.x + a2.x, t0i = a0.y + a2.y;
    const float t1r = a0.x - a2.x, t1i = a0.y - a2.y;
    const float t2r = a1.x + a3.x, t2i = a1.y + a3.y;
    const float t3r = a1.x - a3.x, t3i = a1.y - a3.y;

    X[P2(base)]       = make_float2(t0r + t2r, t0i + t2i);
    X[P2(base + q)]   = make_float2(t1r - t3i, t1i + t3r);
    X[P2(base + 2*q)] = make_float2(t0r - t2r, t0i - t2i);
    X[P2(base + 3*q)] = make_float2(t1r + t3i, t1i - t3r);
}

__global__ __launch_bounds__(THREADS, 2)
void mcf_fft6_kernel(const float* __restrict__ x1,
                     const float* __restrict__ x2,
                     const float* __restrict__ x3,
                     float* __restrict__ out)
{
    __shared__ __align__(16) float2 X[1088];   // 1024 + padding
    __shared__ __align__(16) float2 W[1088];

    const int bx = blockIdx.x;             // 0..191: one transform (row pair)
    const int gr  = 2 * bx;
    const int arr = gr >> 7;
    const int lA  = gr & 127;

    const float* xp = (arr == 0) ? x1 : ((arr == 1) ? x2 : x3);
    const float* xa = xp + (size_t)lA * N_CONV;
    const float* xb = xa + N_CONV;

    const int t = threadIdx.x;

    // Prologue: float4 input loads (issued first for MLP), then twiddles.
    {
        const float4 va = ((const float4*)xa)[t];
        const float4 vb = ((const float4*)xb)[t];

        float sn, cs;
        sincospif((float)t * (1.0f / 512.0f), &sn, &cs);
        W[P2(t)]       = make_float2(cs, -sn);
        W[P2(t + 256)] = make_float2(-sn, -cs);
        W[P2(t + 512)] = make_float2(-cs, sn);
        W[P2(t + 768)] = make_float2(sn, cs);

        const int b = 4 * t;
        X[P2(b)]     = make_float2(va.x, vb.x);
        X[P2(b + 1)] = make_float2(va.y, vb.y);
        X[P2(b + 2)] = make_float2(va.z, vb.z);
        X[P2(b + 3)] = make_float2(va.w, vb.w);
    }
    __syncthreads();

    // Global forward stages.
    fwd_stage<1024>(X, W, t); __syncthreads();
    fwd_stage< 256>(X, W, t); __syncthreads();

    // Warp-local forward stages (points stay within this warp's 128-block).
    fwd_stage<  64>(X, W, t); __syncwarp();
    fwd_stage<  16>(X, W, t); __syncwarp();

    // Fused fwd L=4 (identity twiddles): keep Z in registers, publish to smem.
    float2 Z[4];
    {
        const int b = 4 * t;
        const float2 a0 = X[P2(b)],     a1 = X[P2(b + 1)];
        const float2 a2 = X[P2(b + 2)], a3 = X[P2(b + 3)];
        const float t0r = a0.x + a2.x, t0i = a0.y + a2.y;
        const float t1r = a0.x - a2.x, t1i = a0.y - a2.y;
        const float t2r = a1.x + a3.x, t2i = a1.y + a3.y;
        const float t3r = a1.x - a3.x, t3i = a1.y - a3.y;
        Z[0] = make_float2(t0r + t2r, t0i + t2i);
        Z[1] = make_float2(t1r + t3i, t1i - t3r);   // o1 = t1 - i*t3
        Z[2] = make_float2(t0r - t2r, t0i - t2i);
        Z[3] = make_float2(t1r - t3i, t1i + t3r);   // o3 = t1 + i*t3
        X[P2(b)]     = Z[0];
        X[P2(b + 1)] = Z[1];
        X[P2(b + 2)] = Z[2];
        X[P2(b + 3)] = Z[3];
    }
    __syncthreads();   // middle reads arbitrary (global) mirror positions

    // Middle: conj-symmetry unpack + square + repack (Z local, mirror from
    // smem), then fused inv L=4 after the sync.
    float2 Y[4];
    {
        #pragma unroll
        for (int j = 0; j < 4; ++j) {
            const int p  = 4 * t + j;
            const int k  = rev4(p);
            const int pm = rev4((N_CONV - k) & (N_CONV - 1));

            const float2 Zp = Z[j];
            const float2 M  = X[P2(pm)];

            // Xa = (Z + conj(M))/2 ; Xb = (Z - conj(M))/(2i)
            const float Ar = 0.5f * (Zp.x + M.x), Ai = 0.5f * (Zp.y - M.y);
            const float Br = 0.5f * (Zp.y + M.y), Bi = 0.5f * (M.x - Zp.x);

            const float Yar = Ar*Ar - Ai*Ai, Yai = 2.0f*Ar*Ai;
            const float Ybr = Br*Br - Bi*Bi, Ybi = 2.0f*Br*Bi;
            Y[j] = make_float2(Yar - Ybi, Yai + Ybr);   // Y = Ya + i*Yb
        }
    }
    __syncthreads();   // all mirror reads complete before in-place writes
    {
        const int b = 4 * t;
        const float t0r = Y[0].x + Y[2].x, t0i = Y[0].y + Y[2].y;
        const float t1r = Y[0].x - Y[2].x, t1i = Y[0].y - Y[2].y;
        const float t2r = Y[1].x + Y[3].x, t2i = Y[1].y + Y[3].y;
        const float t3r = Y[1].x - Y[3].x, t3i = Y[1].y - Y[3].y;
        X[P2(b)]     = make_float2(t0r + t2r, t0i + t2i);
        X[P2(b + 1)] = make_float2(t1r - t3i, t1i + t3r);
        X[P2(b + 2)] = make_float2(t0r - t2r, t0i - t2i);
        X[P2(b + 3)] = make_float2(t1r + t3i, t1i - t3r);
    }
    __syncwarp();      // inv16/inv64 consume only this warp's 128-block

    // Warp-local inverse stages.
    inv_stage<  16>(X, W, t); __syncwarp();
    inv_stage<  64>(X, W, t); __syncthreads();   // inv256 is global

    inv_stage< 256>(X, W, t); __syncthreads();

    // Final inverse stage L=1024 (q=256, pos=t): write both rows to gmem.
    {
        const float2 a0 = X[P2(t)];
        float2 a1 = X[P2(t + 256)];
        float2 a2 = X[P2(t + 512)];
        float2 a3 = X[P2(t + 768)];

        float2 w; float r;
        w = W[P2(t)];     r = a1.x;
        a1.x = r*w.x + a1.y*w.y;  a1.y = a1.y*w.x - r*w.y;
        w = W[P2(2*t)];   r = a2.x;
        a2.x = r*w.x + a2.y*w.y;  a2.y = a2.y*w.x - r*w.y;
        w = W[P2(3*t)];   r = a3.x;
        a3.x = r*w.x + a3.y*w.y;  a3.y = a3.y*w.x - r*w.y;

        const float t0r = a0.x + a2.x, t0i = a0.y + a2.y;
        const float t1r = a0.x - a2.x, t1i = a0.y - a2.y;
        const float t2r = a1.x + a3.x, t2i = a1.y + a3.y;
        const float t3r = a1.x - a3.x, t3i = a1.y - a3.y;

        const float inv_n = 1.0f / 1024.0f;
        float* orowA = out + (size_t)arr * 128 * N_CONV + (size_t)lA * N_CONV;
        float* orowB = orowA + N_CONV;

        orowA[t]       = (t0r + t2r) * inv_n;
        orowB[t]       = (t0i + t2i) * inv_n;
        orowA[t + 256] = (t1r - t3i) * inv_n;
        orowB[t + 256] = (t1i + t3r) * inv_n;
        orowA[t + 512] = (t0r - t2r) * inv_n;
        orowB[t + 512] = (t0i - t2i) * inv_n;
        orowA[t + 768] = (t1r + t3i) * inv_n;
        orowB[t + 768] = (t1i - t3r) * inv_n;
    }
}

extern "C" void kernel_launch(void* const* d_in, const int* in_sizes, int n_in,
                              void* d_out, int out_size)
{
    const float* x1 = (const float*)d_in[0];
    const float* x2 = (const float*)d_in[1];
    const float* x3 = (const float*)d_in[2];
    float* out = (float*)d_out;

    mcf_fft6_kernel<<<192, THREADS>>>(x1, x2, x3, out);
}